// round 6
// baseline (speedup 1.0000x reference)
#include <cuda_runtime.h>
#include <cuda_fp16.h>
#include <cstdint>

#define M_TOK 128
#define HID   4096
#define INTER 11008
#define BN    128
#define BK    32
#define NT    256
#define KS1   4            // GEMM1 K-split
#define KS2   8            // GEMM2 K-split

#define RS        80                    // fp16 tile row stride (64B data + 16B pad)
#define RING_A_B  (128 * RS)            // 10240: A fp16 stage
#define RING_W_B  (128 * RS)            // 10240: W fp16 stage
#define STAGE_B   (RING_A_B + RING_W_B) // 20480
#define NSTAGE    4
#define SMEM_BYTES (NSTAGE * STAGE_B)   // 81920

// ---------------- scratch (device globals; no allocation allowed) ----------------
__device__ __align__(16) __half g_xh[M_TOK * HID];
__device__ __align__(16) float  g_up  [KS1 * M_TOK * INTER];
__device__ __align__(16) float  g_gate[KS1 * M_TOK * INTER];
__device__ __align__(16) __half g_h [M_TOK * INTER];
__device__ __align__(16) float  g_p2[KS2 * M_TOK * HID];

// ---------------- helpers ----------------
__device__ __forceinline__ uint32_t smem_u32(const void* p) {
    uint32_t r;
    asm("{ .reg .u64 t; cvta.to.shared.u64 t, %1; cvt.u32.u64 %0, t; }" : "=r"(r) : "l"(p));
    return r;
}

#define CP16(dst, src) \
    asm volatile("cp.async.cg.shared.global [%0], [%1], 16;" :: "r"(dst), "l"(src))
#define CP_COMMIT() asm volatile("cp.async.commit_group;")
#define CP_WAIT2()  asm volatile("cp.async.wait_group 2;")

#define LDSM4(r, a)                                                          \
    asm volatile("ldmatrix.sync.aligned.m8n8.x4.shared.b16 {%0,%1,%2,%3}, [%4];" \
        : "=r"((r)[0]), "=r"((r)[1]), "=r"((r)[2]), "=r"((r)[3]) : "r"(a))

#define MMA16816(c, a, b0, b1)                                               \
    asm volatile("mma.sync.aligned.m16n8k16.row.col.f32.f16.f16.f32 "        \
        "{%0,%1,%2,%3}, {%4,%5,%6,%7}, {%8,%9}, {%0,%1,%2,%3};"              \
        : "+f"((c)[0]), "+f"((c)[1]), "+f"((c)[2]), "+f"((c)[3])             \
        : "r"((a)[0]), "r"((a)[1]), "r"((a)[2]), "r"((a)[3]),                \
          "r"(b0), "r"(b1))

__device__ __forceinline__ uint32_t cvt_h2(float2 f) {
    __half2 h = __float22half2_rn(f);
    return *reinterpret_cast<uint32_t*>(&h);
}

__device__ __forceinline__ float4 ldcg4(const float* p) {
    return __ldcg(reinterpret_cast<const float4*>(p));
}

// load one W stage into registers: thread covers row=tid>>1, cols half*16..+15 (fp32)
__device__ __forceinline__ void load_w(float4* wr, const float* Wrow, int kb) {
    #pragma unroll
    for (int q = 0; q < 4; ++q) wr[q] = ldcg4(Wrow + kb + q * 4);
}

// store register W stage as fp16 into slot
__device__ __forceinline__ void sts_w(uint32_t dst, const float4* wr) {
    uint4 o0, o1;
    o0.x = cvt_h2(make_float2(wr[0].x, wr[0].y));
    o0.y = cvt_h2(make_float2(wr[0].z, wr[0].w));
    o0.z = cvt_h2(make_float2(wr[1].x, wr[1].y));
    o0.w = cvt_h2(make_float2(wr[1].z, wr[1].w));
    o1.x = cvt_h2(make_float2(wr[2].x, wr[2].y));
    o1.y = cvt_h2(make_float2(wr[2].z, wr[2].w));
    o1.z = cvt_h2(make_float2(wr[3].x, wr[3].y));
    o1.w = cvt_h2(make_float2(wr[3].z, wr[3].w));
    asm volatile("st.shared.v4.b32 [%0], {%1,%2,%3,%4};"
        :: "r"(dst), "r"(o0.x), "r"(o0.y), "r"(o0.z), "r"(o0.w));
    asm volatile("st.shared.v4.b32 [%0], {%1,%2,%3,%4};"
        :: "r"(dst + 16), "r"(o1.x), "r"(o1.y), "r"(o1.z), "r"(o1.w));
}

// issue A stage (fp16, cp.async): 2 x 16B per thread
__device__ __forceinline__ void cp_a(uint32_t dA, const __half* __restrict__ A,
                                     int lda, int kb, int tid) {
    #pragma unroll
    for (int i = 0; i < 2; ++i) {
        const int c = tid + i * NT;          // 512 chunks: row=c>>2, col16=c&3
        const int row = c >> 2, col = c & 3;
        CP16(dA + row * RS + col * 16, A + (size_t)row * lda + kb + col * 8);
    }
}

// ============================================================================
// 128x128-tile fp16 HMMA GEMM. A: cp.async ring. W: LDG.cg -> cvt fp16 -> STS.
// Warp layout 2x4 (warp tile 64x32). out_plane[by][m,n0+c] = sum_k A*W (partials)
// ============================================================================
__global__ __launch_bounds__(NT, 2)
void gemm_f16(const float* __restrict__ Wa, float* __restrict__ outa,
              const float* __restrict__ Wb, float* __restrict__ outb,
              int nsplit, int Ntot, int Ktot, int klen,
              const __half* __restrict__ A, int lda)
{
    extern __shared__ __align__(16) char smem[];
    const uint32_t sbase = smem_u32(smem);

    const int tid = threadIdx.x;
    const int l   = tid & 31;
    const int w   = tid >> 5;
    const int wr  = w >> 2;      // 0..1 (64 M-rows)
    const int wc  = w & 3;       // 0..3 (32 N-cols)

    const float* W; float* out; int n0;
    if ((int)blockIdx.x < nsplit) { W = Wa; out = outa; n0 = blockIdx.x * BN; }
    else                          { W = Wb; out = outb; n0 = (blockIdx.x - nsplit) * BN; }
    const int k0 = blockIdx.y * klen;
    out += (size_t)blockIdx.y * M_TOK * Ntot;

    // per-thread W addressing
    const int wrow = tid >> 1, whalf = tid & 1;
    const float* Wrow = W + (size_t)(n0 + wrow) * Ktot + whalf * 16 + k0;
    const uint32_t wsts = (uint32_t)(RING_A_B + wrow * RS + whalf * 32);

    // ldmatrix per-lane offsets
    const int lrow = l & 15;
    const int lkB  = (l >> 4) * 16;
    uint32_t aoff[4], boff[2];
    #pragma unroll
    for (int i = 0; i < 4; ++i)
        aoff[i] = (uint32_t)((wr * 64 + i * 16 + lrow) * RS + lkB);
    #pragma unroll
    for (int j2 = 0; j2 < 2; ++j2)
        boff[j2] = (uint32_t)(RING_A_B + (wc * 32 + j2 * 16 + lrow) * RS + lkB);

    float c[4][4][4];
    #pragma unroll
    for (int i = 0; i < 4; ++i)
        #pragma unroll
        for (int j = 0; j < 4; ++j)
            #pragma unroll
            for (int t = 0; t < 4; ++t) c[i][j][t] = 0.f;

    const int S = klen / BK;
    float4 wreg[4];

    // prologue: W(0) -> smem, W(1) -> regs, A(0..2) in flight
    load_w(wreg, Wrow, 0);
    sts_w(sbase + 0 * STAGE_B + wsts, wreg);
    load_w(wreg, Wrow, BK);
    #pragma unroll
    for (int p = 0; p < NSTAGE - 1; ++p) {
        cp_a(sbase + p * STAGE_B, A, lda, k0 + p * BK, tid);
        CP_COMMIT();
    }

    for (int s = 0; s < S; ++s) {
        const int slot = s & (NSTAGE - 1);
        const uint32_t sA = sbase + slot * STAGE_B;

        CP_WAIT2();             // A(s) arrived
        __syncthreads();        // W(s) STS'd last iter now visible; slots free

        // refill: STS W(s+1) from regs, LDG W(s+2), cp.async A(s+3)
        if (s + 1 < S) sts_w(sbase + ((s + 1) & (NSTAGE - 1)) * STAGE_B + wsts, wreg);
        {
            const int kn = (s + 2 < S) ? (s + 2) * BK : 0;   // clamp (dead data ok)
            load_w(wreg, Wrow, kn);
        }
        if (s + NSTAGE - 1 < S)
            cp_a(sbase + ((s + NSTAGE - 1) & (NSTAGE - 1)) * STAGE_B,
                 A, lda, k0 + (s + NSTAGE - 1) * BK, tid);
        CP_COMMIT();

        // ---- MMA on stage s: A + B via ldmatrix (both fp16) ----
        #pragma unroll
        for (int kk = 0; kk < 2; ++kk) {
            uint32_t afr[4][4], bfr[2][4];
            #pragma unroll
            for (int i = 0; i < 4; ++i)   LDSM4(afr[i], sA + aoff[i] + kk * 32);
            #pragma unroll
            for (int j2 = 0; j2 < 2; ++j2) LDSM4(bfr[j2], sA + boff[j2] + kk * 32);
            #pragma unroll
            for (int i = 0; i < 4; ++i)
                #pragma unroll
                for (int j = 0; j < 4; ++j) {
                    const int j2 = j >> 1, jh = j & 1;
                    MMA16816(c[i][j], afr[i], bfr[j2][jh], bfr[j2][jh + 2]);
                }
        }
    }

    // ---- epilogue: direct float2 stores of C fragments ----
    const int g = l >> 2, q = l & 3;
    #pragma unroll
    for (int i = 0; i < 4; ++i) {
        const int row = wr * 64 + i * 16 + g;
        #pragma unroll
        for (int j = 0; j < 4; ++j) {
            const int col = n0 + wc * 32 + j * 8 + q * 2;
            *reinterpret_cast<float2*>(out + (size_t)row * Ntot + col) =
                make_float2(c[i][j][0], c[i][j][1]);
            *reinterpret_cast<float2*>(out + (size_t)(row + 8) * Ntot + col) =
                make_float2(c[i][j][2], c[i][j][3]);
        }
    }
}

// ============================================================================
// Elementwise kernels (float4-vectorized)
// ============================================================================
__global__ void convert_x_kernel(const float* __restrict__ x) {
    const int i = (blockIdx.x * blockDim.x + threadIdx.x) * 4;
    const float4 v = *reinterpret_cast<const float4*>(x + i);
    uint2 o;
    o.x = cvt_h2(make_float2(v.x, v.y));
    o.y = cvt_h2(make_float2(v.z, v.w));
    *reinterpret_cast<uint2*>(g_xh + i) = o;
}

__device__ __forceinline__ float silu_mul(float u, float g) {
    return (u / (1.0f + expf(-u))) * g;
}

__global__ void swiglu_kernel(const float* __restrict__ w1s,
                              const float* __restrict__ w3s) {
    const int i = (blockIdx.x * blockDim.x + threadIdx.x) * 4;
    const int MI = M_TOK * INTER;
    const int n = i % INTER;
    float4 u = make_float4(0.f, 0.f, 0.f, 0.f);
    float4 t = make_float4(0.f, 0.f, 0.f, 0.f);
    #pragma unroll
    for (int p = 0; p < KS1; ++p) {
        const float4 a = *reinterpret_cast<const float4*>(g_up + i + p * MI);
        const float4 b = *reinterpret_cast<const float4*>(g_gate + i + p * MI);
        u.x += a.x; u.y += a.y; u.z += a.z; u.w += a.w;
        t.x += b.x; t.y += b.y; t.z += b.z; t.w += b.w;
    }
    const float4 s1 = *reinterpret_cast<const float4*>(w1s + n);
    const float4 s3 = *reinterpret_cast<const float4*>(w3s + n);
    float r0 = silu_mul(u.x * s1.x, t.x * s3.x);
    float r1 = silu_mul(u.y * s1.y, t.y * s3.y);
    float r2 = silu_mul(u.z * s1.z, t.z * s3.z);
    float r3 = silu_mul(u.w * s1.w, t.w * s3.w);
    uint2 o;
    o.x = cvt_h2(make_float2(r0, r1));
    o.y = cvt_h2(make_float2(r2, r3));
    *reinterpret_cast<uint2*>(g_h + i) = o;
}

__global__ void reduce_kernel(float* __restrict__ out, const float* __restrict__ w2s) {
    const int i = (blockIdx.x * blockDim.x + threadIdx.x) * 4;
    const int MH = M_TOK * HID;
    float4 s = make_float4(0.f, 0.f, 0.f, 0.f);
    #pragma unroll
    for (int p = 0; p < KS2; ++p) {
        const float4 v = *reinterpret_cast<const float4*>(g_p2 + i + p * MH);
        s.x += v.x; s.y += v.y; s.z += v.z; s.w += v.w;
    }
    const float4 sc = *reinterpret_cast<const float4*>(w2s + (i & (HID - 1)));
    *reinterpret_cast<float4*>(out + i) =
        make_float4(s.x * sc.x, s.y * sc.y, s.z * sc.z, s.w * sc.w);
}

// ============================================================================
// Launch
// ============================================================================
extern "C" void kernel_launch(void* const* d_in, const int* in_sizes, int n_in,
                              void* d_out, int out_size) {
    const float* x   = (const float*)d_in[0];
    const float* w1  = (const float*)d_in[1];
    const float* w1s = (const float*)d_in[2];
    const float* w3  = (const float*)d_in[3];
    const float* w3s = (const float*)d_in[4];
    const float* w2  = (const float*)d_in[5];
    const float* w2s = (const float*)d_in[6];
    float* out = (float*)d_out;

    cudaFuncSetAttribute(gemm_f16,
                         cudaFuncAttributeMaxDynamicSharedMemorySize, SMEM_BYTES);

    void *xh, *up, *gate, *h, *p2;
    cudaGetSymbolAddress(&xh, g_xh);
    cudaGetSymbolAddress(&up, g_up);
    cudaGetSymbolAddress(&gate, g_gate);
    cudaGetSymbolAddress(&h, g_h);
    cudaGetSymbolAddress(&p2, g_p2);

    // 1. x -> fp16
    convert_x_kernel<<<(M_TOK * HID) / (4 * 256), 256>>>(x);

    // 2. GEMM1: up (w1) + gate (w3), K-split 4 -> 688 CTAs
    gemm_f16<<<dim3(2 * (INTER / BN), KS1), NT, SMEM_BYTES>>>(
        w1, (float*)up, w3, (float*)gate,
        INTER / BN, INTER, HID, HID / KS1,
        (const __half*)xh, HID);

    // 3. SwiGLU (sums K-split planes, applies per-channel scales) -> fp16 h
    swiglu_kernel<<<(M_TOK * INTER) / (4 * 256), 256>>>(w1s, w3s);

    // 4. GEMM2: K-split 8 -> 256 CTAs
    gemm_f16<<<dim3(HID / BN, KS2), NT, SMEM_BYTES>>>(
        w2, (float*)p2, w2, (float*)p2,
        HID / BN, HID, INTER, INTER / KS2,
        (const __half*)h, INTER);

    // 5. reduce K-split planes + w2_s scale
    reduce_kernel<<<(M_TOK * HID) / (4 * 256), 256>>>(out, w2s);
}

// round 7
// speedup vs baseline: 1.3361x; 1.3361x over previous
#include <cuda_runtime.h>
#include <cuda_fp16.h>
#include <cstdint>

#define M_TOK 128
#define HID   4096
#define INTER 11008
#define BN    64
#define BK    32
#define NT    128
#define KS1   4            // GEMM1 K-split
#define KS2   8            // GEMM2 K-split

#define RS        80                    // fp16 A-tile row stride (64B data + 16B pad)
#define RING_A_B  (128 * RS)            // 10240: A fp16 stage (128 rows)
#define RING_W_B  (BN * 128)            // 8192:  W fp32 stage (64 rows, swizzled)
#define STAGE_B   (RING_A_B + RING_W_B) // 18432
#define NSTAGE    4
#define SMEM_BYTES (NSTAGE * STAGE_B)   // 73728

// ---------------- scratch (device globals; no allocation allowed) ----------------
__device__ __align__(16) __half g_xh[M_TOK * HID];
__device__ __align__(16) float  g_up  [KS1 * M_TOK * INTER];
__device__ __align__(16) float  g_gate[KS1 * M_TOK * INTER];
__device__ __align__(16) __half g_h [M_TOK * INTER];
__device__ __align__(16) float  g_p2[KS2 * M_TOK * HID];

// ---------------- helpers ----------------
__device__ __forceinline__ uint32_t smem_u32(const void* p) {
    uint32_t r;
    asm("{ .reg .u64 t; cvta.to.shared.u64 t, %1; cvt.u32.u64 %0, t; }" : "=r"(r) : "l"(p));
    return r;
}

#define CP16(dst, src) \
    asm volatile("cp.async.cg.shared.global [%0], [%1], 16;" :: "r"(dst), "l"(src))
#define CP_COMMIT() asm volatile("cp.async.commit_group;")
#define CP_WAIT2()  asm volatile("cp.async.wait_group 2;")

#define LDSM4(r, a)                                                          \
    asm volatile("ldmatrix.sync.aligned.m8n8.x4.shared.b16 {%0,%1,%2,%3}, [%4];" \
        : "=r"((r)[0]), "=r"((r)[1]), "=r"((r)[2]), "=r"((r)[3]) : "r"(a))

#define MMA16816(c, a, b0, b1)                                               \
    asm volatile("mma.sync.aligned.m16n8k16.row.col.f32.f16.f16.f32 "        \
        "{%0,%1,%2,%3}, {%4,%5,%6,%7}, {%8,%9}, {%0,%1,%2,%3};"              \
        : "+f"((c)[0]), "+f"((c)[1]), "+f"((c)[2]), "+f"((c)[3])             \
        : "r"((a)[0]), "r"((a)[1]), "r"((a)[2]), "r"((a)[3]),                \
          "r"(b0), "r"(b1))

__device__ __forceinline__ uint32_t cvt_h2(float2 f) {
    __half2 h = __float22half2_rn(f);
    return *reinterpret_cast<uint32_t*>(&h);
}

// issue one pipeline stage: A fp16 (4 x 16B / thread) + W fp32 swizzled (4 x 16B / thread)
__device__ __forceinline__ void issue_stage(
    uint32_t sbase, int slot, const __half* __restrict__ A, int lda,
    const float* __restrict__ W, int Ktot, int n0, int kb, int tid)
{
    const uint32_t dA = sbase + slot * STAGE_B;
    const uint32_t dW = dA + RING_A_B;
    #pragma unroll
    for (int i = 0; i < 4; ++i) {
        const int c = tid + i * NT;          // 512 chunks: row = c>>2, col16 = c&3
        const int row = c >> 2, col = c & 3;
        CP16(dA + row * RS + col * 16, A + (size_t)row * lda + kb + col * 8);
    }
    #pragma unroll
    for (int i = 0; i < 4; ++i) {
        const int c = tid + i * NT;          // 512 chunks: row = c>>3 (0..63), col = c&7
        const int row = c >> 3, col = c & 7;
        const uint32_t off = (uint32_t)(row * 128 + ((col * 16) ^ ((row & 3) * 32)));
        CP16(dW + off, W + (size_t)(n0 + row) * Ktot + kb + col * 4);
    }
}

// ============================================================================
// 128x64-tile fp16 HMMA GEMM, 4-slot cp.async ring, B-frags direct from fp32.
// 128 threads, warp layout 2(M) x 2(N); per-warp tile 64x32 (same as R5 inner loop).
//   out_plane[by][m, n0+c] = sum_k A[m,k] * W[n,k]   (partials, no scale)
// ============================================================================
__global__ __launch_bounds__(NT, 3)
void gemm_f16(const float* __restrict__ Wa, float* __restrict__ outa,
              const float* __restrict__ Wb, float* __restrict__ outb,
              int nsplit, int Ntot, int Ktot, int klen,
              const __half* __restrict__ A, int lda)
{
    extern __shared__ __align__(16) char smem[];
    const uint32_t sbase = smem_u32(smem);

    const int tid = threadIdx.x;
    const int l   = tid & 31;
    const int w   = tid >> 5;
    const int wr  = w >> 1;      // 0..1 (64 M-rows)
    const int wc  = w & 1;       // 0..1 (32 N-cols)

    const float* W; float* out; int n0;
    if ((int)blockIdx.x < nsplit) { W = Wa; out = outa; n0 = blockIdx.x * BN; }
    else                          { W = Wb; out = outb; n0 = (blockIdx.x - nsplit) * BN; }
    const int k0 = blockIdx.y * klen;
    out += (size_t)blockIdx.y * M_TOK * Ntot;

    // A ldmatrix per-lane offsets (4 x 16-row fragments per warp)
    const int lrow = l & 15;
    const int lkB  = (l >> 4) * 16;
    uint32_t aoff[4];
    #pragma unroll
    for (int i = 0; i < 4; ++i)
        aoff[i] = (uint32_t)((wr * 64 + i * 16 + lrow) * RS + lkB);

    // B-fragment per-lane constants (fp32 LDS.64 path)
    const int nl = l >> 2;                       // n within 8-block
    const int q8 = (l & 3) * 8;                  // k byte offset (2 fp32)
    const uint32_t sw = (uint32_t)((nl & 3) * 32);

    float c[4][4][4];
    #pragma unroll
    for (int i = 0; i < 4; ++i)
        #pragma unroll
        for (int j = 0; j < 4; ++j)
            #pragma unroll
            for (int t = 0; t < 4; ++t) c[i][j][t] = 0.f;

    const int S = klen / BK;

    // prologue: 3 stages in flight
    #pragma unroll
    for (int p = 0; p < NSTAGE - 1; ++p) {
        issue_stage(sbase, p, A, lda, W, Ktot, n0, k0 + p * BK, tid);
        CP_COMMIT();
    }

    for (int s = 0; s < S; ++s) {
        const int slot = s & (NSTAGE - 1);
        const uint32_t sA = sbase + slot * STAGE_B;
        const char* wB = smem + slot * STAGE_B + RING_A_B;

        CP_WAIT2();             // group s complete
        __syncthreads();        // refill slot is free (consumed at s-1)

        if (s + NSTAGE - 1 < S)
            issue_stage(sbase, (s + NSTAGE - 1) & (NSTAGE - 1),
                        A, lda, W, Ktot, n0, k0 + (s + NSTAGE - 1) * BK, tid);
        CP_COMMIT();

        // ---- MMA on stage s: A via ldmatrix, B via LDS.64 + cvt ----
        #pragma unroll
        for (int kk = 0; kk < 2; ++kk) {
            uint32_t afr[4][4];
            #pragma unroll
            for (int i = 0; i < 4; ++i) LDSM4(afr[i], sA + aoff[i] + kk * 32);

            const uint32_t o0 = ((uint32_t)(kk * 64 + q8)) ^ sw;
            const uint32_t o1 = o0 ^ 32u;
            #pragma unroll
            for (int j2 = 0; j2 < 2; ++j2) {
                const char* r0p = wB + (wc * 32 + j2 * 16 + nl) * 128;
                const char* r1p = r0p + 8 * 128;
                const float2 f00 = *reinterpret_cast<const float2*>(r0p + o0);
                const float2 f01 = *reinterpret_cast<const float2*>(r0p + o1);
                const float2 f10 = *reinterpret_cast<const float2*>(r1p + o0);
                const float2 f11 = *reinterpret_cast<const float2*>(r1p + o1);
                const uint32_t b00 = cvt_h2(f00), b01 = cvt_h2(f01);
                const uint32_t b10 = cvt_h2(f10), b11 = cvt_h2(f11);
                #pragma unroll
                for (int i = 0; i < 4; ++i) {
                    MMA16816(c[i][j2 * 2 + 0], afr[i], b00, b01);
                    MMA16816(c[i][j2 * 2 + 1], afr[i], b10, b11);
                }
            }
        }
    }

    // ---- epilogue: direct float2 stores of C fragments ----
    const int g = l >> 2, q = l & 3;
    #pragma unroll
    for (int i = 0; i < 4; ++i) {
        const int row = wr * 64 + i * 16 + g;
        #pragma unroll
        for (int j = 0; j < 4; ++j) {
            const int col = n0 + wc * 32 + j * 8 + q * 2;
            *reinterpret_cast<float2*>(out + (size_t)row * Ntot + col) =
                make_float2(c[i][j][0], c[i][j][1]);
            *reinterpret_cast<float2*>(out + (size_t)(row + 8) * Ntot + col) =
                make_float2(c[i][j][2], c[i][j][3]);
        }
    }
}

// ============================================================================
// Elementwise kernels (float4-vectorized)
// ============================================================================
__global__ void convert_x_kernel(const float* __restrict__ x) {
    const int i = (blockIdx.x * blockDim.x + threadIdx.x) * 4;
    const float4 v = *reinterpret_cast<const float4*>(x + i);
    uint2 o;
    o.x = cvt_h2(make_float2(v.x, v.y));
    o.y = cvt_h2(make_float2(v.z, v.w));
    *reinterpret_cast<uint2*>(g_xh + i) = o;
}

__device__ __forceinline__ float silu_mul(float u, float g) {
    return (u / (1.0f + expf(-u))) * g;
}

__global__ void swiglu_kernel(const float* __restrict__ w1s,
                              const float* __restrict__ w3s) {
    const int i = (blockIdx.x * blockDim.x + threadIdx.x) * 4;
    const int MI = M_TOK * INTER;
    const int n = i % INTER;
    float4 u = make_float4(0.f, 0.f, 0.f, 0.f);
    float4 t = make_float4(0.f, 0.f, 0.f, 0.f);
    #pragma unroll
    for (int p = 0; p < KS1; ++p) {
        const float4 a = *reinterpret_cast<const float4*>(g_up + i + p * MI);
        const float4 b = *reinterpret_cast<const float4*>(g_gate + i + p * MI);
        u.x += a.x; u.y += a.y; u.z += a.z; u.w += a.w;
        t.x += b.x; t.y += b.y; t.z += b.z; t.w += b.w;
    }
    const float4 s1 = *reinterpret_cast<const float4*>(w1s + n);
    const float4 s3 = *reinterpret_cast<const float4*>(w3s + n);
    float r0 = silu_mul(u.x * s1.x, t.x * s3.x);
    float r1 = silu_mul(u.y * s1.y, t.y * s3.y);
    float r2 = silu_mul(u.z * s1.z, t.z * s3.z);
    float r3 = silu_mul(u.w * s1.w, t.w * s3.w);
    uint2 o;
    o.x = cvt_h2(make_float2(r0, r1));
    o.y = cvt_h2(make_float2(r2, r3));
    *reinterpret_cast<uint2*>(g_h + i) = o;
}

__global__ void reduce_kernel(float* __restrict__ out, const float* __restrict__ w2s) {
    const int i = (blockIdx.x * blockDim.x + threadIdx.x) * 4;
    const int MH = M_TOK * HID;
    float4 s = make_float4(0.f, 0.f, 0.f, 0.f);
    #pragma unroll
    for (int p = 0; p < KS2; ++p) {
        const float4 v = *reinterpret_cast<const float4*>(g_p2 + i + p * MH);
        s.x += v.x; s.y += v.y; s.z += v.z; s.w += v.w;
    }
    const float4 sc = *reinterpret_cast<const float4*>(w2s + (i & (HID - 1)));
    *reinterpret_cast<float4*>(out + i) =
        make_float4(s.x * sc.x, s.y * sc.y, s.z * sc.z, s.w * sc.w);
}

// ============================================================================
// Launch
// ============================================================================
extern "C" void kernel_launch(void* const* d_in, const int* in_sizes, int n_in,
                              void* d_out, int out_size) {
    const float* x   = (const float*)d_in[0];
    const float* w1  = (const float*)d_in[1];
    const float* w1s = (const float*)d_in[2];
    const float* w3  = (const float*)d_in[3];
    const float* w3s = (const float*)d_in[4];
    const float* w2  = (const float*)d_in[5];
    const float* w2s = (const float*)d_in[6];
    float* out = (float*)d_out;

    cudaFuncSetAttribute(gemm_f16,
                         cudaFuncAttributeMaxDynamicSharedMemorySize, SMEM_BYTES);

    void *xh, *up, *gate, *h, *p2;
    cudaGetSymbolAddress(&xh, g_xh);
    cudaGetSymbolAddress(&up, g_up);
    cudaGetSymbolAddress(&gate, g_gate);
    cudaGetSymbolAddress(&h, g_h);
    cudaGetSymbolAddress(&p2, g_p2);

    // 1. x -> fp16
    convert_x_kernel<<<(M_TOK * HID) / (4 * 256), 256>>>(x);

    // 2. GEMM1: up (w1) + gate (w3), BN=64 tiles, K-split 4 -> 1376 CTAs
    gemm_f16<<<dim3(2 * (INTER / BN), KS1), NT, SMEM_BYTES>>>(
        w1, (float*)up, w3, (float*)gate,
        INTER / BN, INTER, HID, HID / KS1,
        (const __half*)xh, HID);

    // 3. SwiGLU (sums K-split planes, applies per-channel scales) -> fp16 h
    swiglu_kernel<<<(M_TOK * INTER) / (4 * 256), 256>>>(w1s, w3s);

    // 4. GEMM2: BN=64 tiles, K-split 8 -> 512 CTAs
    gemm_f16<<<dim3(HID / BN, KS2), NT, SMEM_BYTES>>>(
        w2, (float*)p2, w2, (float*)p2,
        HID / BN, HID, INTER, INTER / KS2,
        (const __half*)h, INTER);

    // 5. reduce K-split planes + w2_s scale
    reduce_kernel<<<(M_TOK * HID) / (4 * 256), 256>>>(out, w2s);
}